// round 13
// baseline (speedup 1.0000x reference)
#include <cuda_runtime.h>
#include <cuda_fp16.h>
#include <cstdint>

#define B_ROWS 65536
#define D_IN   784
#define KP     832      // K padded to 13 slabs of 64
#define D_H    300
#define DHP    304      // padded h width (stride)
#define BNP    320      // padded binarized-W1 rows
#define D_OUT  10
#define EPSV   1e-5f
#define G1M    512                 // m-blocks (partials per column)
#define G1_BLOCKS (G1M * 2)        // 1024: x2 n-halves
#define G2_BLOCKS (B_ROWS / 64)    // 1024
#define NSLAB  13

// ---------------- scratch ---------------------------------------------------
__device__ __align__(16) __half g_Bh1[BNP * KP];            // sign(W1) fp16, zero-padded
__device__ __align__(16) __half g_B2h[16 * DHP];            // sign(W2) fp16 16x304
__device__ __align__(16) __half g_h[(size_t)B_ROWS * DHP];  // layer-1 pre-BN output
__device__ __align__(16) float  g_part1s[DHP * G1M];
__device__ __align__(16) float  g_part1q[DHP * G1M];
__device__ __align__(16) float  g_ab1[2 * DHP];
__device__ __align__(16) float  g_part2[G2_BLOCKS * 20];
__device__ __align__(16) float  g_ab2[2 * D_OUT];

__device__ __forceinline__ uint32_t smem_u32(const void* p) {
    uint32_t a;
    asm("{ .reg .u64 t; cvta.to.shared.u64 t, %1; cvt.u32.u64 %0, t; }" : "=r"(a) : "l"(p));
    return a;
}

#define MMA16816(acc, a0,a1,a2,a3, b0,b1)                                      \
    asm volatile(                                                              \
        "mma.sync.aligned.m16n8k16.row.col.f32.f16.f16.f32 "                   \
        "{%0,%1,%2,%3}, {%4,%5,%6,%7}, {%8,%9}, {%0,%1,%2,%3};\n"              \
        : "+f"(acc[0]), "+f"(acc[1]), "+f"(acc[2]), "+f"(acc[3])               \
        : "r"(a0), "r"(a1), "r"(a2), "r"(a3), "r"(b0), "r"(b1))

#define LDSM_X4(r0,r1,r2,r3, addr)                                             \
    asm volatile("ldmatrix.sync.aligned.m8n8.x4.shared.b16 {%0,%1,%2,%3}, [%4];" \
        : "=r"(r0), "=r"(r1), "=r"(r2), "=r"(r3) : "r"(addr))

#define CP_ASYNC16(dst, src)                                                   \
    asm volatile("cp.async.cg.shared.global [%0], [%1], 16;"                   \
        :: "r"(dst), "l"(src) : "memory")
#define CP_COMMIT() asm volatile("cp.async.commit_group;" ::: "memory")
#define CP_WAIT0()  asm volatile("cp.async.wait_group 0;" ::: "memory")

// ---------------- prep: binarize weights ----------------------------------
__global__ void prep_kernel(const float* __restrict__ W1, const float* __restrict__ W2) {
    int i = blockIdx.x * blockDim.x + threadIdx.x;
    const int n1 = BNP * KP;
    if (i < n1) {
        int n = i / KP, k = i - n * KP;
        float v = 0.f;
        if (n < D_H && k < D_IN) v = (W1[n * D_IN + k] >= 0.f) ? 1.f : -1.f;
        g_Bh1[i] = __float2half_rn(v);
    } else {
        int j = i - n1;
        if (j < 16 * DHP) {
            int r = j / DHP, c = j - r * DHP;
            float v = 0.f;
            if (r < D_OUT && c < D_H) v = (W2[r * D_H + c] >= 0.f) ? 1.f : -1.f;
            g_B2h[j] = __float2half_rn(v);
        }
    }
}

// ---------------- GEMM1 (unchanged round-12): h = x@sign(W1)^T + partials --
#define A_SLAB 18432u
#define B_SLAB 23040u
#define B_BASE 36864u
#define SMEM1_TOTAL (2 * 18432 + 2 * 23040)   // 82944

__global__ __launch_bounds__(256, 2) void gemm1_kernel(const float* __restrict__ x) {
    extern __shared__ __align__(128) char smem[];
    const uint32_t sb = smem_u32(smem);
    const int tid  = threadIdx.x;
    const int wid  = tid >> 5, lane = tid & 31;
    const int wm   = wid & 3,  wn   = wid >> 2;    // 4m x 2n
    const int g    = lane >> 2, tg  = lane & 3;
    const int mblk = blockIdx.x >> 1;
    const int m0   = mblk * 128;
    const int n0   = (blockIdx.x & 1) * 160;

    float acc[2][10][4];
#pragma unroll
    for (int mt = 0; mt < 2; mt++)
#pragma unroll
        for (int nt = 0; nt < 10; nt++)
#pragma unroll
            for (int e = 0; e < 4; e++) acc[mt][nt][e] = 0.f;

    const uint32_t aAddr = sb + (uint32_t)((wm * 32 + (lane & 15)) * 144 + (lane >> 4) * 16);
    const uint32_t bAddr = sb + B_BASE
        + (uint32_t)((wn * 80 + (lane & 7) + ((lane >> 4) << 3)) * 144 + ((lane >> 3) & 1) * 16);

    const float* xBase = x + (size_t)m0 * D_IN;
    float4 aR[4];

#define LDG_A(S, H)                                                              \
    do {                                                                         \
        const int kb = (S) * 64 + (H) * 32;                                      \
        _Pragma("unroll")                                                        \
        for (int j = 0; j < 4; j++) {                                            \
            const int e = tid + 256 * j, row = e >> 3, c4 = (e & 7) * 4;         \
            aR[j] = (kb + c4 < D_IN)                                             \
                ? __ldcs((const float4*)(xBase + (size_t)row * D_IN + kb + c4))  \
                : make_float4(0.f, 0.f, 0.f, 0.f);                               \
        }                                                                        \
    } while (0)

#define STS_A(BUF, H)                                                            \
    do {                                                                         \
        const uint32_t aoff = (BUF) * A_SLAB + (H) * 64u;                        \
        _Pragma("unroll")                                                        \
        for (int j = 0; j < 4; j++) {                                            \
            const int e = tid + 256 * j, row = e >> 3, c4 = (e & 7) * 4;         \
            __half2 h0 = __floats2half2_rn(aR[j].x, aR[j].y);                    \
            __half2 h1 = __floats2half2_rn(aR[j].z, aR[j].w);                    \
            uint2 v;                                                             \
            v.x = *(uint32_t*)&h0; v.y = *(uint32_t*)&h1;                        \
            *(uint2*)(smem + aoff + row * 144 + c4 * 2) = v;                     \
        }                                                                        \
    } while (0)

#define CPB_SLAB(S, BUF)                                                         \
    do {                                                                         \
        const int kb = (S) * 64;                                                 \
        const uint32_t boff = B_BASE + (BUF) * B_SLAB;                           \
        _Pragma("unroll")                                                        \
        for (int j = 0; j < 5; j++) {                                            \
            const int u = tid + 256 * j;                                         \
            CP_ASYNC16(sb + boff + (u >> 3) * 144 + (u & 7) * 16,                \
                       g_Bh1 + (size_t)(n0 + (u >> 3)) * KP + kb + (u & 7) * 8); \
        }                                                                        \
    } while (0)

#define COMPUTE_K2(BUF, KK0)                                                     \
    do {                                                                         \
        const uint32_t ab = aAddr + (BUF) * A_SLAB;                              \
        const uint32_t bb = bAddr + (BUF) * B_SLAB;                              \
        _Pragma("unroll")                                                        \
        for (int kk = (KK0); kk < (KK0) + 2; kk++) {                             \
            uint32_t a0[4], a1[4];                                               \
            LDSM_X4(a0[0], a0[1], a0[2], a0[3], ab + kk * 32);                   \
            LDSM_X4(a1[0], a1[1], a1[2], a1[3], ab + 2304 + kk * 32);            \
            _Pragma("unroll")                                                    \
            for (int p = 0; p < 5; p++) {                                        \
                uint32_t b0, b1, b2, b3;                                         \
                LDSM_X4(b0, b1, b2, b3, bb + p * 2304 + kk * 32);                \
                MMA16816(acc[0][2 * p],     a0[0], a0[1], a0[2], a0[3], b0, b1); \
                MMA16816(acc[1][2 * p],     a1[0], a1[1], a1[2], a1[3], b0, b1); \
                MMA16816(acc[0][2 * p + 1], a0[0], a0[1], a0[2], a0[3], b2, b3); \
                MMA16816(acc[1][2 * p + 1], a1[0], a1[1], a1[2], a1[3], b2, b3); \
            }                                                                    \
        }                                                                        \
    } while (0)

    CPB_SLAB(0, 0);
    CP_COMMIT();
    LDG_A(0, 0); STS_A(0, 0);
    LDG_A(0, 1); STS_A(0, 1);
    CP_WAIT0();
    __syncthreads();

    for (int s = 0; s < NSLAB; s++) {
        const int buf = s & 1;
        if (s < NSLAB - 1) {
            CPB_SLAB(s + 1, buf ^ 1);
            CP_COMMIT();
            LDG_A(s + 1, 0);
        }
        COMPUTE_K2(buf, 0);
        if (s < NSLAB - 1) {
            STS_A(buf ^ 1, 0);
            LDG_A(s + 1, 1);
        }
        COMPUTE_K2(buf, 2);
        if (s < NSLAB - 1) {
            STS_A(buf ^ 1, 1);
            CP_WAIT0();
        }
        __syncthreads();
    }
#undef LDG_A
#undef STS_A
#undef CPB_SLAB
#undef COMPUTE_K2

#pragma unroll
    for (int mt = 0; mt < 2; mt++) {
        const int row0 = m0 + wm * 32 + mt * 16 + g;
#pragma unroll
        for (int nt = 0; nt < 10; nt++) {
            const int col = n0 + wn * 80 + nt * 8 + tg * 2;
            if (col < DHP) {
                *(__half2*)&g_h[(size_t)row0 * DHP + col]       = __floats2half2_rn(acc[mt][nt][0], acc[mt][nt][1]);
                *(__half2*)&g_h[(size_t)(row0 + 8) * DHP + col] = __floats2half2_rn(acc[mt][nt][2], acc[mt][nt][3]);
            }
        }
    }

    float* sp = (float*)smem;
#pragma unroll
    for (int nt = 0; nt < 10; nt++) {
        float s0 = 0.f, s1 = 0.f, q0 = 0.f, q1 = 0.f;
#pragma unroll
        for (int mt = 0; mt < 2; mt++) {
            const float v0 = acc[mt][nt][0], v1 = acc[mt][nt][1];
            const float v2 = acc[mt][nt][2], v3 = acc[mt][nt][3];
            s0 += v0 + v2;  s1 += v1 + v3;
            q0 += v0 * v0 + v2 * v2;  q1 += v1 * v1 + v3 * v3;
        }
#pragma unroll
        for (int o = 4; o < 32; o <<= 1) {
            s0 += __shfl_xor_sync(0xffffffffu, s0, o);
            s1 += __shfl_xor_sync(0xffffffffu, s1, o);
            q0 += __shfl_xor_sync(0xffffffffu, q0, o);
            q1 += __shfl_xor_sync(0xffffffffu, q1, o);
        }
        if (g == 0) {
            const int lc = wn * 80 + nt * 8 + tg * 2;
            sp[wm * 160 + lc]           = s0;
            sp[wm * 160 + lc + 1]       = s1;
            sp[640 + wm * 160 + lc]     = q0;
            sp[640 + wm * 160 + lc + 1] = q1;
        }
    }
    __syncthreads();
    if (tid < 160) {
        const int col = n0 + tid;
        if (col < DHP) {
            float s = 0.f, q = 0.f;
#pragma unroll
            for (int w = 0; w < 4; w++) { s += sp[w * 160 + tid]; q += sp[640 + w * 160 + tid]; }
            g_part1s[(size_t)col * G1M + mblk] = s;
            g_part1q[(size_t)col * G1M + mblk] = q;
        }
    }
}

// ---------------- reduce1: one block per column (512 partials) -------------
__global__ void reduce1_kernel(const float* __restrict__ gamma1, const float* __restrict__ beta1) {
    __shared__ float ss[8], qq[8];
    const int col = blockIdx.x, t = threadIdx.x;   // 256 threads
    float s = g_part1s[(size_t)col * G1M + t] + g_part1s[(size_t)col * G1M + t + 256];
    float q = g_part1q[(size_t)col * G1M + t] + g_part1q[(size_t)col * G1M + t + 256];
#pragma unroll
    for (int o = 16; o > 0; o >>= 1) {
        s += __shfl_xor_sync(0xffffffffu, s, o);
        q += __shfl_xor_sync(0xffffffffu, q, o);
    }
    if ((t & 31) == 0) { ss[t >> 5] = s; qq[t >> 5] = q; }
    __syncthreads();
    if (t == 0) {
        float S = 0.f, Q = 0.f;
#pragma unroll
        for (int w = 0; w < 8; w++) { S += ss[w]; Q += qq[w]; }
        const float inv = 1.f / (float)B_ROWS;
        const float mean = S * inv;
        const float var  = Q * inv - mean * mean;
        float a = 0.f, b = 0.f;
        if (col < D_H) {
            a = gamma1[col] * rsqrtf(var + EPSV);
            b = beta1[col] - mean * a;
        }
        g_ab1[col] = a;
        g_ab1[DHP + col] = b;
    }
}

// ---------------- GEMM2: M=64 / 128-thread retile for occupancy ------------
// o = h @ (sign(W2) o a)^T + c.  Same per-warp work as the proven version
// (4 warps x 16 rows), but 64-row tile -> 39.9KB dyn smem -> 4-5 CTAs/SM,
// so bulk loads/preambles overlap across CTAs. Grid 1024.
#define STG2_STRIDE 624
#define SMEM2_DYN   (64 * STG2_STRIDE)   // 39936 B

__global__ __launch_bounds__(128) void gemm2_kernel(float* __restrict__ out) {
    extern __shared__ __align__(128) char dsm[];   // A stage
    __shared__ __align__(16) __half Bs2[16][312];
    __shared__ float cs[16];
    __shared__ float ps[4][12], qs[4][12];

    const int tid = threadIdx.x, w = tid >> 5, lane = tid & 31;
    const int g = lane >> 2, tg = lane & 3;
    const int m0 = blockIdx.x * 64;
    const uint32_t astg = smem_u32(dsm);

    // 1) bulk copy of the 64-row h tile (2432 x 16B, coalesced, one group)
    const char* hsrc = (const char*)(g_h + (size_t)m0 * DHP);
#pragma unroll
    for (int j = 0; j < 19; j++) {
        const int i = tid + 128 * j;          // 0..2431
        const int row = i / 38, q = i - row * 38;
        CP_ASYNC16(astg + row * STG2_STRIDE + q * 16, hsrc + row * 608 + q * 16);
    }
    CP_COMMIT();

    // 2) overlap: stage S' = sign(W2)*a ; c[j] = b . sign(W2)[j]
    for (int i = tid; i < 16 * DHP; i += 128) {
        const int r = i / DHP, k = i - r * DHP;
        Bs2[r][k] = __float2half_rn(__half2float(g_B2h[i]) * g_ab1[k]);
    }
    for (int j = w; j < D_OUT; j += 4) {
        float s = 0.f;
        for (int k = lane; k < D_H; k += 32)
            s += g_ab1[DHP + k] * __half2float(g_B2h[j * DHP + k]);
#pragma unroll
        for (int o = 16; o > 0; o >>= 1) s += __shfl_xor_sync(0xffffffffu, s, o);
        if (lane == 0) cs[j] = s;
    }
    if (tid >= D_OUT && tid < 16) cs[tid] = 0.f;

    // 3) single wait + single barrier
    CP_WAIT0();
    __syncthreads();

    // 4) pure-smem k-loop (warp-level code identical to proven version)
    const uint32_t ldsmA = astg + (uint32_t)((w * 16 + (lane & 15)) * STG2_STRIDE + (lane >> 4) * 16);
    float acc[2][4];
#pragma unroll
    for (int nt = 0; nt < 2; nt++)
#pragma unroll
        for (int e = 0; e < 4; e++) acc[nt][e] = 0.f;

#pragma unroll
    for (int kb = 0; kb < 19; kb++) {
        uint32_t a0, a1, a2, a3;
        LDSM_X4(a0, a1, a2, a3, ldsmA + kb * 32);
        const uint32_t b00 = *(const uint32_t*)&Bs2[g]    [kb * 16 + tg * 2];
        const uint32_t b01 = *(const uint32_t*)&Bs2[g]    [kb * 16 + tg * 2 + 8];
        const uint32_t b10 = *(const uint32_t*)&Bs2[8 + g][kb * 16 + tg * 2];
        const uint32_t b11 = *(const uint32_t*)&Bs2[8 + g][kb * 16 + tg * 2 + 8];
        MMA16816(acc[0], a0, a1, a2, a3, b00, b01);
        MMA16816(acc[1], a0, a1, a2, a3, b10, b11);
    }

    // 5) epilogue: add c, store, BN2 partials
    const int row0 = m0 + w * 16 + g;
    const float c00 = cs[tg * 2], c01 = cs[tg * 2 + 1];
    const float c10 = cs[8 + tg * 2], c11 = cs[9 + tg * 2];
    const float o00 = acc[0][0] + c00, o01 = acc[0][1] + c01;
    const float o02 = acc[0][2] + c00, o03 = acc[0][3] + c01;
    const float o10 = acc[1][0] + c10, o11 = acc[1][1] + c11;
    const float o12 = acc[1][2] + c10, o13 = acc[1][3] + c11;

    *(float2*)&out[(size_t)row0 * D_OUT + tg * 2]       = make_float2(o00, o01);
    *(float2*)&out[(size_t)(row0 + 8) * D_OUT + tg * 2] = make_float2(o02, o03);
    if (tg == 0) {
        *(float2*)&out[(size_t)row0 * D_OUT + 8]       = make_float2(o10, o11);
        *(float2*)&out[(size_t)(row0 + 8) * D_OUT + 8] = make_float2(o12, o13);
    }

    {
        float s0 = o00 + o02, s1 = o01 + o03;
        float q0 = o00 * o00 + o02 * o02, q1 = o01 * o01 + o03 * o03;
        float s2 = o10 + o12, s3 = o11 + o13;
        float q2 = o10 * o10 + o12 * o12, q3 = o11 * o11 + o13 * o13;
#pragma unroll
        for (int o = 4; o < 32; o <<= 1) {
            s0 += __shfl_xor_sync(0xffffffffu, s0, o);
            s1 += __shfl_xor_sync(0xffffffffu, s1, o);
            q0 += __shfl_xor_sync(0xffffffffu, q0, o);
            q1 += __shfl_xor_sync(0xffffffffu, q1, o);
            s2 += __shfl_xor_sync(0xffffffffu, s2, o);
            s3 += __shfl_xor_sync(0xffffffffu, s3, o);
            q2 += __shfl_xor_sync(0xffffffffu, q2, o);
            q3 += __shfl_xor_sync(0xffffffffu, q3, o);
        }
        if (g == 0) {
            const int c0 = tg * 2;
            ps[w][c0] = s0; ps[w][c0 + 1] = s1;
            qs[w][c0] = q0; qs[w][c0 + 1] = q1;
            if (tg == 0) {
                ps[w][8] = s2; ps[w][9] = s3;
                qs[w][8] = q2; qs[w][9] = q3;
            }
        }
    }
    __syncthreads();
    if (tid < D_OUT) {
        float s = 0.f, q = 0.f;
#pragma unroll
        for (int w2 = 0; w2 < 4; w2++) { s += ps[w2][tid]; q += qs[w2][tid]; }
        g_part2[blockIdx.x * 20 + tid] = s;
        g_part2[blockIdx.x * 20 + D_OUT + tid] = q;
    }
}

__global__ void reduce2_kernel(const float* __restrict__ gamma2, const float* __restrict__ beta2) {
    __shared__ float ss[256], qq[256];
    const int t = threadIdx.x, j = blockIdx.x;
    float s = 0.f, q = 0.f;
    for (int i = t; i < G2_BLOCKS; i += 256) {
        s += g_part2[i * 20 + j];
        q += g_part2[i * 20 + D_OUT + j];
    }
    ss[t] = s; qq[t] = q; __syncthreads();
    for (int o = 128; o > 0; o >>= 1) {
        if (t < o) { ss[t] += ss[t + o]; qq[t] += qq[t + o]; }
        __syncthreads();
    }
    if (t == 0) {
        const float inv = 1.f / (float)B_ROWS;
        const float mean = ss[0] * inv;
        const float var  = qq[0] * inv - mean * mean;
        const float a = gamma2[j] * rsqrtf(var + EPSV);
        g_ab2[j] = a;
        g_ab2[D_OUT + j] = beta2[j] - mean * a;
    }
}

__global__ void apply_kernel(float* __restrict__ out) {
    const int i = blockIdx.x * blockDim.x + threadIdx.x;
    if (i < B_ROWS * D_OUT) {
        const int j = i % D_OUT;
        out[i] = fmaf(out[i], g_ab2[j], g_ab2[D_OUT + j]);
    }
}

// ---------------- launch ---------------------------------------------------
extern "C" void kernel_launch(void* const* d_in, const int* in_sizes, int n_in,
                              void* d_out, int out_size) {
    const float* x      = (const float*)d_in[0];
    const float* W1     = (const float*)d_in[1];
    const float* gamma1 = (const float*)d_in[2];
    const float* beta1  = (const float*)d_in[3];
    const float* W2     = (const float*)d_in[4];
    const float* gamma2 = (const float*)d_in[5];
    const float* beta2  = (const float*)d_in[6];
    float* out = (float*)d_out;

    cudaFuncSetAttribute(gemm1_kernel, cudaFuncAttributeMaxDynamicSharedMemorySize, SMEM1_TOTAL);
    cudaFuncSetAttribute(gemm2_kernel, cudaFuncAttributeMaxDynamicSharedMemorySize, SMEM2_DYN);

    const int prepN = BNP * KP + 16 * DHP;
    prep_kernel<<<(prepN + 255) / 256, 256>>>(W1, W2);
    gemm1_kernel<<<G1_BLOCKS, 256, SMEM1_TOTAL>>>(x);
    reduce1_kernel<<<DHP, 256>>>(gamma1, beta1);
    gemm2_kernel<<<G2_BLOCKS, 128, SMEM2_DYN>>>(out);
    reduce2_kernel<<<D_OUT, 256>>>(gamma2, beta2);
    apply_kernel<<<(B_ROWS * D_OUT + 255) / 256, 256>>>(out);
}

// round 14
// speedup vs baseline: 1.0696x; 1.0696x over previous
#include <cuda_runtime.h>
#include <cuda_fp16.h>
#include <cstdint>

#define B_ROWS 65536
#define D_IN   784
#define KP     832      // K padded to 13 slabs of 64
#define D_H    300
#define DHP    304      // padded h width (stride)
#define BNP    320      // padded binarized-W1 rows
#define D_OUT  10
#define EPSV   1e-5f
#define G1M    512                 // m-blocks (partials per column)
#define G1_BLOCKS (G1M * 2)        // 1024: x2 n-halves
#define G2_BLOCKS (B_ROWS / 128)   // 512
#define NSLAB  13

// ---------------- scratch ---------------------------------------------------
__device__ __align__(16) __half g_Bh1[BNP * KP];            // sign(W1) fp16, zero-padded
__device__ __align__(16) __half g_B2h[16 * DHP];            // sign(W2) fp16 16x304
__device__ __align__(16) __half g_h[(size_t)B_ROWS * DHP];  // layer-1 pre-BN output
__device__ __align__(16) float  g_part1s[DHP * G1M];
__device__ __align__(16) float  g_part1q[DHP * G1M];
__device__ __align__(16) float  g_ab1[2 * DHP];
__device__ __align__(16) float  g_part2[G2_BLOCKS * 20];
__device__ __align__(16) float  g_ab2[2 * D_OUT];

__device__ __forceinline__ uint32_t smem_u32(const void* p) {
    uint32_t a;
    asm("{ .reg .u64 t; cvta.to.shared.u64 t, %1; cvt.u32.u64 %0, t; }" : "=r"(a) : "l"(p));
    return a;
}

#define MMA16816(acc, a0,a1,a2,a3, b0,b1)                                      \
    asm volatile(                                                              \
        "mma.sync.aligned.m16n8k16.row.col.f32.f16.f16.f32 "                   \
        "{%0,%1,%2,%3}, {%4,%5,%6,%7}, {%8,%9}, {%0,%1,%2,%3};\n"              \
        : "+f"(acc[0]), "+f"(acc[1]), "+f"(acc[2]), "+f"(acc[3])               \
        : "r"(a0), "r"(a1), "r"(a2), "r"(a3), "r"(b0), "r"(b1))

#define LDSM_X4(r0,r1,r2,r3, addr)                                             \
    asm volatile("ldmatrix.sync.aligned.m8n8.x4.shared.b16 {%0,%1,%2,%3}, [%4];" \
        : "=r"(r0), "=r"(r1), "=r"(r2), "=r"(r3) : "r"(addr))

#define CP_ASYNC16(dst, src)                                                   \
    asm volatile("cp.async.cg.shared.global [%0], [%1], 16;"                   \
        :: "r"(dst), "l"(src) : "memory")
#define CP_COMMIT() asm volatile("cp.async.commit_group;" ::: "memory")
#define CP_WAIT0()  asm volatile("cp.async.wait_group 0;" ::: "memory")

// ---------------- prep: binarize weights ----------------------------------
__global__ void prep_kernel(const float* __restrict__ W1, const float* __restrict__ W2) {
    int i = blockIdx.x * blockDim.x + threadIdx.x;
    const int n1 = BNP * KP;
    if (i < n1) {
        int n = i / KP, k = i - n * KP;
        float v = 0.f;
        if (n < D_H && k < D_IN) v = (W1[n * D_IN + k] >= 0.f) ? 1.f : -1.f;
        g_Bh1[i] = __float2half_rn(v);
    } else {
        int j = i - n1;
        if (j < 16 * DHP) {
            int r = j / DHP, c = j - r * DHP;
            float v = 0.f;
            if (r < D_OUT && c < D_H) v = (W2[r * D_H + c] >= 0.f) ? 1.f : -1.f;
            g_B2h[j] = __float2half_rn(v);
        }
    }
}

// ---------------- GEMM1: h = x@sign(W1)^T + BN1 partials -------------------
// Round-12 structure + N-trim: half-1 (n0=160) wn=1 warps skip the p=4
// n-pair (cols 304..319, zero-padded B) -> -10% tensor issue in those blocks.
#define A_SLAB 18432u
#define B_SLAB 23040u
#define B_BASE 36864u
#define SMEM1_TOTAL (2 * 18432 + 2 * 23040)   // 82944

__global__ __launch_bounds__(256, 2) void gemm1_kernel(const float* __restrict__ x) {
    extern __shared__ __align__(128) char smem[];
    const uint32_t sb = smem_u32(smem);
    const int tid  = threadIdx.x;
    const int wid  = tid >> 5, lane = tid & 31;
    const int wm   = wid & 3,  wn   = wid >> 2;    // 4m x 2n
    const int g    = lane >> 2, tg  = lane & 3;
    const int mblk = blockIdx.x >> 1;
    const int m0   = mblk * 128;
    const int n0   = (blockIdx.x & 1) * 160;
    const int plim = (n0 == 0 || wn == 0) ? 5 : 4;   // skip zero-padded n-pair

    float acc[2][10][4];
#pragma unroll
    for (int mt = 0; mt < 2; mt++)
#pragma unroll
        for (int nt = 0; nt < 10; nt++)
#pragma unroll
            for (int e = 0; e < 4; e++) acc[mt][nt][e] = 0.f;

    const uint32_t aAddr = sb + (uint32_t)((wm * 32 + (lane & 15)) * 144 + (lane >> 4) * 16);
    const uint32_t bAddr = sb + B_BASE
        + (uint32_t)((wn * 80 + (lane & 7) + ((lane >> 4) << 3)) * 144 + ((lane >> 3) & 1) * 16);

    const float* xBase = x + (size_t)m0 * D_IN;
    float4 aR[4];

#define LDG_A(S, H)                                                              \
    do {                                                                         \
        const int kb = (S) * 64 + (H) * 32;                                      \
        _Pragma("unroll")                                                        \
        for (int j = 0; j < 4; j++) {                                            \
            const int e = tid + 256 * j, row = e >> 3, c4 = (e & 7) * 4;         \
            aR[j] = (kb + c4 < D_IN)                                             \
                ? __ldcs((const float4*)(xBase + (size_t)row * D_IN + kb + c4))  \
                : make_float4(0.f, 0.f, 0.f, 0.f);                               \
        }                                                                        \
    } while (0)

#define STS_A(BUF, H)                                                            \
    do {                                                                         \
        const uint32_t aoff = (BUF) * A_SLAB + (H) * 64u;                        \
        _Pragma("unroll")                                                        \
        for (int j = 0; j < 4; j++) {                                            \
            const int e = tid + 256 * j, row = e >> 3, c4 = (e & 7) * 4;         \
            __half2 h0 = __floats2half2_rn(aR[j].x, aR[j].y);                    \
            __half2 h1 = __floats2half2_rn(aR[j].z, aR[j].w);                    \
            uint2 v;                                                             \
            v.x = *(uint32_t*)&h0; v.y = *(uint32_t*)&h1;                        \
            *(uint2*)(smem + aoff + row * 144 + c4 * 2) = v;                     \
        }                                                                        \
    } while (0)

#define CPB_SLAB(S, BUF)                                                         \
    do {                                                                         \
        const int kb = (S) * 64;                                                 \
        const uint32_t boff = B_BASE + (BUF) * B_SLAB;                           \
        _Pragma("unroll")                                                        \
        for (int j = 0; j < 5; j++) {                                            \
            const int u = tid + 256 * j;                                         \
            CP_ASYNC16(sb + boff + (u >> 3) * 144 + (u & 7) * 16,                \
                       g_Bh1 + (size_t)(n0 + (u >> 3)) * KP + kb + (u & 7) * 8); \
        }                                                                        \
    } while (0)

#define COMPUTE_K2(BUF, KK0)                                                     \
    do {                                                                         \
        const uint32_t ab = aAddr + (BUF) * A_SLAB;                              \
        const uint32_t bb = bAddr + (BUF) * B_SLAB;                              \
        _Pragma("unroll")                                                        \
        for (int kk = (KK0); kk < (KK0) + 2; kk++) {                             \
            uint32_t a0[4], a1[4];                                               \
            LDSM_X4(a0[0], a0[1], a0[2], a0[3], ab + kk * 32);                   \
            LDSM_X4(a1[0], a1[1], a1[2], a1[3], ab + 2304 + kk * 32);            \
            _Pragma("unroll")                                                    \
            for (int p = 0; p < 5; p++) {                                        \
                if (p < plim) {                                                  \
                    uint32_t b0, b1, b2, b3;                                     \
                    LDSM_X4(b0, b1, b2, b3, bb + p * 2304 + kk * 32);            \
                    MMA16816(acc[0][2 * p],     a0[0], a0[1], a0[2], a0[3], b0, b1); \
                    MMA16816(acc[1][2 * p],     a1[0], a1[1], a1[2], a1[3], b0, b1); \
                    MMA16816(acc[0][2 * p + 1], a0[0], a0[1], a0[2], a0[3], b2, b3); \
                    MMA16816(acc[1][2 * p + 1], a1[0], a1[1], a1[2], a1[3], b2, b3); \
                }                                                                \
            }                                                                    \
        }                                                                        \
    } while (0)

    CPB_SLAB(0, 0);
    CP_COMMIT();
    LDG_A(0, 0); STS_A(0, 0);
    LDG_A(0, 1); STS_A(0, 1);
    CP_WAIT0();
    __syncthreads();

    for (int s = 0; s < NSLAB; s++) {
        const int buf = s & 1;
        if (s < NSLAB - 1) {
            CPB_SLAB(s + 1, buf ^ 1);
            CP_COMMIT();
            LDG_A(s + 1, 0);
        }
        COMPUTE_K2(buf, 0);
        if (s < NSLAB - 1) {
            STS_A(buf ^ 1, 0);
            LDG_A(s + 1, 1);
        }
        COMPUTE_K2(buf, 2);
        if (s < NSLAB - 1) {
            STS_A(buf ^ 1, 1);
            CP_WAIT0();
        }
        __syncthreads();
    }
#undef LDG_A
#undef STS_A
#undef CPB_SLAB
#undef COMPUTE_K2

#pragma unroll
    for (int mt = 0; mt < 2; mt++) {
        const int row0 = m0 + wm * 32 + mt * 16 + g;
#pragma unroll
        for (int nt = 0; nt < 10; nt++) {
            const int col = n0 + wn * 80 + nt * 8 + tg * 2;
            if (col < DHP) {
                *(__half2*)&g_h[(size_t)row0 * DHP + col]       = __floats2half2_rn(acc[mt][nt][0], acc[mt][nt][1]);
                *(__half2*)&g_h[(size_t)(row0 + 8) * DHP + col] = __floats2half2_rn(acc[mt][nt][2], acc[mt][nt][3]);
            }
        }
    }

    float* sp = (float*)smem;
#pragma unroll
    for (int nt = 0; nt < 10; nt++) {
        float s0 = 0.f, s1 = 0.f, q0 = 0.f, q1 = 0.f;
#pragma unroll
        for (int mt = 0; mt < 2; mt++) {
            const float v0 = acc[mt][nt][0], v1 = acc[mt][nt][1];
            const float v2 = acc[mt][nt][2], v3 = acc[mt][nt][3];
            s0 += v0 + v2;  s1 += v1 + v3;
            q0 += v0 * v0 + v2 * v2;  q1 += v1 * v1 + v3 * v3;
        }
#pragma unroll
        for (int o = 4; o < 32; o <<= 1) {
            s0 += __shfl_xor_sync(0xffffffffu, s0, o);
            s1 += __shfl_xor_sync(0xffffffffu, s1, o);
            q0 += __shfl_xor_sync(0xffffffffu, q0, o);
            q1 += __shfl_xor_sync(0xffffffffu, q1, o);
        }
        if (g == 0) {
            const int lc = wn * 80 + nt * 8 + tg * 2;
            sp[wm * 160 + lc]           = s0;
            sp[wm * 160 + lc + 1]       = s1;
            sp[640 + wm * 160 + lc]     = q0;
            sp[640 + wm * 160 + lc + 1] = q1;
        }
    }
    __syncthreads();
    if (tid < 160) {
        const int col = n0 + tid;
        if (col < DHP) {
            float s = 0.f, q = 0.f;
#pragma unroll
            for (int w = 0; w < 4; w++) { s += sp[w * 160 + tid]; q += sp[640 + w * 160 + tid]; }
            g_part1s[(size_t)col * G1M + mblk] = s;
            g_part1q[(size_t)col * G1M + mblk] = q;
        }
    }
}

// ---------------- reduce1: one block per column (512 partials) -------------
__global__ void reduce1_kernel(const float* __restrict__ gamma1, const float* __restrict__ beta1) {
    __shared__ float ss[8], qq[8];
    const int col = blockIdx.x, t = threadIdx.x;   // 256 threads
    float s = g_part1s[(size_t)col * G1M + t] + g_part1s[(size_t)col * G1M + t + 256];
    float q = g_part1q[(size_t)col * G1M + t] + g_part1q[(size_t)col * G1M + t + 256];
#pragma unroll
    for (int o = 16; o > 0; o >>= 1) {
        s += __shfl_xor_sync(0xffffffffu, s, o);
        q += __shfl_xor_sync(0xffffffffu, q, o);
    }
    if ((t & 31) == 0) { ss[t >> 5] = s; qq[t >> 5] = q; }
    __syncthreads();
    if (t == 0) {
        float S = 0.f, Q = 0.f;
#pragma unroll
        for (int w = 0; w < 8; w++) { S += ss[w]; Q += qq[w]; }
        const float inv = 1.f / (float)B_ROWS;
        const float mean = S * inv;
        const float var  = Q * inv - mean * mean;
        float a = 0.f, b = 0.f;
        if (col < D_H) {
            a = gamma1[col] * rsqrtf(var + EPSV);
            b = beta1[col] - mean * a;
        }
        g_ab1[col] = a;
        g_ab1[DHP + col] = b;
    }
}

// ---------------- GEMM2: bulk-smem M=128 (round-12 winner, reverted) -------
#define STG2_STRIDE 624
#define SMEM2_DYN   (128 * STG2_STRIDE)   // 79872 B

__global__ __launch_bounds__(256, 1) void gemm2_kernel(float* __restrict__ out) {
    extern __shared__ __align__(128) char dsm[];   // A stage
    __shared__ __align__(16) __half Bs2[16][312];
    __shared__ float cs[16];
    __shared__ float ps[8][12], qs[8][12];

    const int tid = threadIdx.x, w = tid >> 5, lane = tid & 31;
    const int g = lane >> 2, tg = lane & 3;
    const int m0 = blockIdx.x * 128;
    const uint32_t astg = smem_u32(dsm);

    const char* hsrc = (const char*)(g_h + (size_t)m0 * DHP);
#pragma unroll
    for (int j = 0; j < 19; j++) {
        const int i = tid + 256 * j;
        const int row = i / 38, q = i - row * 38;
        CP_ASYNC16(astg + row * STG2_STRIDE + q * 16, hsrc + row * 608 + q * 16);
    }
    CP_COMMIT();

    for (int i = tid; i < 16 * DHP; i += 256) {
        const int r = i / DHP, k = i - r * DHP;
        Bs2[r][k] = __float2half_rn(__half2float(g_B2h[i]) * g_ab1[k]);
    }
    for (int j = w; j < D_OUT; j += 8) {
        float s = 0.f;
        for (int k = lane; k < D_H; k += 32)
            s += g_ab1[DHP + k] * __half2float(g_B2h[j * DHP + k]);
#pragma unroll
        for (int o = 16; o > 0; o >>= 1) s += __shfl_xor_sync(0xffffffffu, s, o);
        if (lane == 0) cs[j] = s;
    }
    if (tid >= D_OUT && tid < 16) cs[tid] = 0.f;

    CP_WAIT0();
    __syncthreads();

    const uint32_t ldsmA = astg + (uint32_t)((w * 16 + (lane & 15)) * STG2_STRIDE + (lane >> 4) * 16);
    float acc[2][4];
#pragma unroll
    for (int nt = 0; nt < 2; nt++)
#pragma unroll
        for (int e = 0; e < 4; e++) acc[nt][e] = 0.f;

#pragma unroll
    for (int kb = 0; kb < 19; kb++) {
        uint32_t a0, a1, a2, a3;
        LDSM_X4(a0, a1, a2, a3, ldsmA + kb * 32);
        const uint32_t b00 = *(const uint32_t*)&Bs2[g]    [kb * 16 + tg * 2];
        const uint32_t b01 = *(const uint32_t*)&Bs2[g]    [kb * 16 + tg * 2 + 8];
        const uint32_t b10 = *(const uint32_t*)&Bs2[8 + g][kb * 16 + tg * 2];
        const uint32_t b11 = *(const uint32_t*)&Bs2[8 + g][kb * 16 + tg * 2 + 8];
        MMA16816(acc[0], a0, a1, a2, a3, b00, b01);
        MMA16816(acc[1], a0, a1, a2, a3, b10, b11);
    }

    const int row0 = m0 + w * 16 + g;
    const float c00 = cs[tg * 2], c01 = cs[tg * 2 + 1];
    const float c10 = cs[8 + tg * 2], c11 = cs[9 + tg * 2];
    const float o00 = acc[0][0] + c00, o01 = acc[0][1] + c01;
    const float o02 = acc[0][2] + c00, o03 = acc[0][3] + c01;
    const float o10 = acc[1][0] + c10, o11 = acc[1][1] + c11;
    const float o12 = acc[1][2] + c10, o13 = acc[1][3] + c11;

    *(float2*)&out[(size_t)row0 * D_OUT + tg * 2]       = make_float2(o00, o01);
    *(float2*)&out[(size_t)(row0 + 8) * D_OUT + tg * 2] = make_float2(o02, o03);
    if (tg == 0) {
        *(float2*)&out[(size_t)row0 * D_OUT + 8]       = make_float2(o10, o11);
        *(float2*)&out[(size_t)(row0 + 8) * D_OUT + 8] = make_float2(o12, o13);
    }

    {
        float s0 = o00 + o02, s1 = o01 + o03;
        float q0 = o00 * o00 + o02 * o02, q1 = o01 * o01 + o03 * o03;
        float s2 = o10 + o12, s3 = o11 + o13;
        float q2 = o10 * o10 + o12 * o12, q3 = o11 * o11 + o13 * o13;
#pragma unroll
        for (int o = 4; o < 32; o <<= 1) {
            s0 += __shfl_xor_sync(0xffffffffu, s0, o);
            s1 += __shfl_xor_sync(0xffffffffu, s1, o);
            q0 += __shfl_xor_sync(0xffffffffu, q0, o);
            q1 += __shfl_xor_sync(0xffffffffu, q1, o);
            s2 += __shfl_xor_sync(0xffffffffu, s2, o);
            s3 += __shfl_xor_sync(0xffffffffu, s3, o);
            q2 += __shfl_xor_sync(0xffffffffu, q2, o);
            q3 += __shfl_xor_sync(0xffffffffu, q3, o);
        }
        if (g == 0) {
            const int c0 = tg * 2;
            ps[w][c0] = s0; ps[w][c0 + 1] = s1;
            qs[w][c0] = q0; qs[w][c0 + 1] = q1;
            if (tg == 0) {
                ps[w][8] = s2; ps[w][9] = s3;
                qs[w][8] = q2; qs[w][9] = q3;
            }
        }
    }
    __syncthreads();
    if (tid < D_OUT) {
        float s = 0.f, q = 0.f;
#pragma unroll
        for (int w2 = 0; w2 < 8; w2++) { s += ps[w2][tid]; q += qs[w2][tid]; }
        g_part2[blockIdx.x * 20 + tid] = s;
        g_part2[blockIdx.x * 20 + D_OUT + tid] = q;
    }
}

__global__ void reduce2_kernel(const float* __restrict__ gamma2, const float* __restrict__ beta2) {
    __shared__ float ss[256], qq[256];
    const int t = threadIdx.x, j = blockIdx.x;
    float s = 0.f, q = 0.f;
    for (int i = t; i < G2_BLOCKS; i += 256) {
        s += g_part2[i * 20 + j];
        q += g_part2[i * 20 + D_OUT + j];
    }
    ss[t] = s; qq[t] = q; __syncthreads();
    for (int o = 128; o > 0; o >>= 1) {
        if (t < o) { ss[t] += ss[t + o]; qq[t] += qq[t + o]; }
        __syncthreads();
    }
    if (t == 0) {
        const float inv = 1.f / (float)B_ROWS;
        const float mean = ss[0] * inv;
        const float var  = qq[0] * inv - mean * mean;
        const float a = gamma2[j] * rsqrtf(var + EPSV);
        g_ab2[j] = a;
        g_ab2[D_OUT + j] = beta2[j] - mean * a;
    }
}

__global__ void apply_kernel(float* __restrict__ out) {
    const int i = blockIdx.x * blockDim.x + threadIdx.x;
    if (i < B_ROWS * D_OUT) {
        const int j = i % D_OUT;
        out[i] = fmaf(out[i], g_ab2[j], g_ab2[D_OUT + j]);
    }
}

// ---------------- launch ---------------------------------------------------
extern "C" void kernel_launch(void* const* d_in, const int* in_sizes, int n_in,
                              void* d_out, int out_size) {
    const float* x      = (const float*)d_in[0];
    const float* W1     = (const float*)d_in[1];
    const float* gamma1 = (const float*)d_in[2];
    const float* beta1  = (const float*)d_in[3];
    const float* W2     = (const float*)d_in[4];
    const float* gamma2 = (const float*)d_in[5];
    const float* beta2  = (const float*)d_in[6];
    float* out = (float*)d_out;

    cudaFuncSetAttribute(gemm1_kernel, cudaFuncAttributeMaxDynamicSharedMemorySize, SMEM1_TOTAL);
    cudaFuncSetAttribute(gemm2_kernel, cudaFuncAttributeMaxDynamicSharedMemorySize, SMEM2_DYN);

    const int prepN = BNP * KP + 16 * DHP;
    prep_kernel<<<(prepN + 255) / 256, 256>>>(W1, W2);
    gemm1_kernel<<<G1_BLOCKS, 256, SMEM1_TOTAL>>>(x);
    reduce1_kernel<<<DHP, 256>>>(gamma1, beta1);
    gemm2_kernel<<<G2_BLOCKS, 256, SMEM2_DYN>>>(out);
    reduce2_kernel<<<D_OUT, 256>>>(gamma2, beta2);
    apply_kernel<<<(B_ROWS * D_OUT + 255) / 256, 256>>>(out);
}